// round 1
// baseline (speedup 1.0000x reference)
#include <cuda_runtime.h>
#include <math.h>

// Problem constants (fixed shapes from reference setup_inputs)
#define BATCH 32768
#define NLEN  1116
#define HDIM  100

// sym4 decomposition filters (from reference)
__constant__ float c_LO[8] = {
    -0.010597401784997278f,  0.032883011666982945f,  0.030841381835986965f,
    -0.18703481171888114f,  -0.02798376941698385f,   0.6308807679295904f,
     0.7148465705525415f,    0.23037781330885523f};
__constant__ float c_HI[8] = {
    -0.23037781330885523f,   0.7148465705525415f,   -0.6308807679295904f,
    -0.02798376941698385f,   0.18703481171888114f,   0.030841381835986965f,
    -0.032883011666982945f, -0.010597401784997278f};

__device__ __forceinline__ float softt(float v, float t) {
    float av = fabsf(v);
    return (av > t) ? copysignf(av - t, v) : 0.0f;
}

// ---------------------------------------------------------------------------
// Kernel 1: per-row 7-level DWT -> soft threshold -> IDWT, writes recon.
// One block (128 threads) per row. All work in shared memory.
// Level lengths: 1116 -> 561 -> 284 -> 145 -> 76 -> 41 -> 24 -> 15
// ---------------------------------------------------------------------------
__global__ __launch_bounds__(128) void wavelet_kernel(
    const float* __restrict__ x,
    const float* __restrict__ thr,
    float* __restrict__ recon)
{
    __shared__ float bufA[1136];
    __shared__ float bufB[1136];
    __shared__ float dbuf[1148];

    const int tid = threadIdx.x;
    const int row = blockIdx.x;
    const float t = fmaxf(thr[0], 0.01f);

    const int ns[8]   = {1116, 561, 284, 145, 76, 41, 24, 15};
    const int doff[7] = {0, 561, 845, 990, 1066, 1107, 1131};

    // Load x into bufA with halo offset 6 (xp = pad(x, (6,7)))
    {
        const float* xr = x + (size_t)row * NLEN;
        for (int i = tid; i < NLEN; i += 128) bufA[6 + i] = xr[i];
        if (tid < 6) bufA[tid] = 0.0f;
        if (tid < 8) bufA[6 + NLEN + tid] = 0.0f;
    }
    __syncthreads();

    // ---------------- Analysis: 7 DWT levels ----------------
    float* cur = bufA;
    float* nxt = bufB;
#pragma unroll
    for (int l = 0; l < 7; ++l) {
        const int m = ns[l + 1];
        float* dd = dbuf + doff[l];
        for (int j = tid; j < m; j += 128) {
            const int base = 2 * j;   // buffer already padded: xp[i] == cur[i]
            float lo = 0.0f, hi = 0.0f;
#pragma unroll
            for (int tt = 0; tt < 8; ++tt) {
                float v = cur[base + tt];
                lo = fmaf(v, c_LO[7 - tt], lo);
                hi = fmaf(v, c_HI[7 - tt], hi);
            }
            nxt[6 + j] = lo;
            dd[j] = softt(hi, t);     // soft-threshold details at store time
        }
        // zero halos of next approx buffer
        if (tid < 6) nxt[tid] = 0.0f;
        if (tid < 8) nxt[6 + m + tid] = 0.0f;
        __syncthreads();
        float* tmp = cur; cur = nxt; nxt = tmp;
    }

    // Soft-threshold the final approximation (length 15), in place.
    if (tid < 15) cur[6 + tid] = softt(cur[6 + tid], t);
    __syncthreads();

    // ---------------- Synthesis: 7 IDWT levels ----------------
    // y[j] (j even): sum_q a[j/2+q]*LO[2q+1] + d[j/2+q]*HI[2q+1]
    // y[j] (j odd) : sum_q a[(j-1)/2+q]*LO[2q] + d[(j-1)/2+q]*HI[2q]
    // Equal-length a/d at every step (the reference's trim is automatic:
    // IDWT never reads index m of a trimmed a).
    const float* abase = cur;   // after 7 levels, cur == bufB
    int aoff = 6;               // a7 stored with halo offset
    float* obase = nxt;         // == bufA
#pragma unroll
    for (int l = 6; l >= 0; --l) {
        const int m = ns[l + 1];
        const int olen = 2 * m - 6;
        const float* a = abase + aoff;
        const float* dd = dbuf + doff[l];
        for (int j = tid; j < olen; j += 128) {
            float y;
            if ((j & 1) == 0) {
                const int i0 = j >> 1;
                y =        a[i0    ] * c_LO[1] + dd[i0    ] * c_HI[1];
                y = fmaf(  a[i0 + 1],  c_LO[3], y); y = fmaf(dd[i0 + 1], c_HI[3], y);
                y = fmaf(  a[i0 + 2],  c_LO[5], y); y = fmaf(dd[i0 + 2], c_HI[5], y);
                y = fmaf(  a[i0 + 3],  c_LO[7], y); y = fmaf(dd[i0 + 3], c_HI[7], y);
            } else {
                const int i0 = (j - 1) >> 1;
                y =        a[i0    ] * c_LO[0] + dd[i0    ] * c_HI[0];
                y = fmaf(  a[i0 + 1],  c_LO[2], y); y = fmaf(dd[i0 + 1], c_HI[2], y);
                y = fmaf(  a[i0 + 2],  c_LO[4], y); y = fmaf(dd[i0 + 2], c_HI[4], y);
                y = fmaf(  a[i0 + 3],  c_LO[6], y); y = fmaf(dd[i0 + 3], c_HI[6], y);
            }
            obase[j] = y;
        }
        __syncthreads();
        float* told = (float*)abase;
        abase = obase; aoff = 0;
        obase = told;
    }

    // Final recon (length 1116) is in abase[0..1115]; write out.
    {
        float* out = recon + (size_t)row * NLEN;
        const float* a = abase;
        for (int i = tid; i < NLEN; i += 128) out[i] = a[i];
    }
}

// ---------------------------------------------------------------------------
// Kernel 2: reg[row] = sum_c sigmoid(recon[row,:]·W1[c,:] + b1[c]) * W2[c] + b2
// Tiled fp32 GEMM: BM=64 rows, all 100 cols (padded to 112), BK=16.
// 256 threads: thread (tr,tc) = (tid>>4, tid&15) owns 4 rows x 7 cols.
// ---------------------------------------------------------------------------
#define BM 64
#define BK 16
#define CPAD 112

__global__ __launch_bounds__(256) void mlp_kernel(
    const float* __restrict__ recon,
    const float* __restrict__ W1,
    const float* __restrict__ b1,
    const float* __restrict__ W2,
    const float* __restrict__ b2,
    float* __restrict__ reg)
{
    __shared__ float As[BK][BM + 1];     // [k][row]
    __shared__ float Bs[BK][CPAD + 1];   // [k][col], 113 stride kills bank conflicts
    __shared__ float red[BM][17];

    const int tid = threadIdx.x;
    const int tr = tid >> 4;     // 0..15 -> rows tr*4 .. tr*4+3
    const int tc = tid & 15;     // 0..15 -> cols tc + 16*cc
    const int row0 = blockIdx.x * BM;

    float acc[4][7];
#pragma unroll
    for (int i = 0; i < 4; ++i)
#pragma unroll
        for (int c = 0; c < 7; ++c) acc[i][c] = 0.0f;

    for (int k0 = 0; k0 < NLEN; k0 += BK) {
        // Load A tile: 64 rows x 16 k
#pragma unroll
        for (int p = 0; p < 4; ++p) {
            int e = tid + p * 256;        // 0..1023
            int r = e >> 4;
            int kk = e & 15;
            int k = k0 + kk;
            As[kk][r] = (k < NLEN) ? recon[(size_t)(row0 + r) * NLEN + k] : 0.0f;
        }
        // Load B tile: 16 k x 112 cols (zero-padded beyond 100)
#pragma unroll
        for (int p = 0; p < 7; ++p) {
            int e = tid + p * 256;        // 0..1791
            int c = e >> 4;
            int kk = e & 15;
            int k = k0 + kk;
            Bs[kk][c] = (c < HDIM && k < NLEN) ? W1[(size_t)c * NLEN + k] : 0.0f;
        }
        __syncthreads();

#pragma unroll
        for (int kk = 0; kk < BK; ++kk) {
            float af[4], bf[7];
#pragma unroll
            for (int i = 0; i < 4; ++i) af[i] = As[kk][tr * 4 + i];
#pragma unroll
            for (int c = 0; c < 7; ++c) bf[c] = Bs[kk][tc + 16 * c];
#pragma unroll
            for (int i = 0; i < 4; ++i)
#pragma unroll
                for (int c = 0; c < 7; ++c)
                    acc[i][c] = fmaf(af[i], bf[c], acc[i][c]);
        }
        __syncthreads();
    }

    // Epilogue: sigmoid + weighted partial sum over this thread's cols
    float part[4] = {0.0f, 0.0f, 0.0f, 0.0f};
#pragma unroll
    for (int cc = 0; cc < 7; ++cc) {
        const int c = tc + 16 * cc;
        const float bb = (c < HDIM) ? b1[c] : 0.0f;
        const float w2 = (c < HDIM) ? W2[c] : 0.0f;
#pragma unroll
        for (int i = 0; i < 4; ++i) {
            float pre = acc[i][cc] + bb;
            float h = 1.0f / (1.0f + __expf(-pre));
            part[i] += h * w2;
        }
    }
#pragma unroll
    for (int i = 0; i < 4; ++i) red[tr * 4 + i][tc] = part[i];
    __syncthreads();

    if (tid < BM) {
        float s = 0.0f;
#pragma unroll
        for (int q = 0; q < 16; ++q) s += red[tid][q];
        reg[row0 + tid] = s + b2[0];
    }
}

// ---------------------------------------------------------------------------
// Launch: d_in order = {x, raw_threshold, W1, b1, W2, b2}
// d_out layout = recon (32768*1116) followed by reg (32768)
// ---------------------------------------------------------------------------
extern "C" void kernel_launch(void* const* d_in, const int* in_sizes, int n_in,
                              void* d_out, int out_size)
{
    const float* x   = (const float*)d_in[0];
    const float* thr = (const float*)d_in[1];
    const float* W1  = (const float*)d_in[2];
    const float* b1  = (const float*)d_in[3];
    const float* W2  = (const float*)d_in[4];
    const float* b2  = (const float*)d_in[5];

    float* recon = (float*)d_out;
    float* reg   = (float*)d_out + (size_t)BATCH * NLEN;

    wavelet_kernel<<<BATCH, 128>>>(x, thr, recon);
    mlp_kernel<<<BATCH / BM, 256>>>(recon, W1, b1, W2, b2, reg);
}

// round 5
// speedup vs baseline: 1.6266x; 1.6266x over previous
#include <cuda_runtime.h>
#include <cuda_bf16.h>
#include <mma.h>
#include <cstdint>
#include <math.h>

using namespace nvcuda;

#define BATCH 32768
#define NLEN  1116
#define HDIM  100

// ---------------------------------------------------------------------------
// sym4 filters
// ---------------------------------------------------------------------------
__constant__ float c_LO[8] = {
    -0.010597401784997278f,  0.032883011666982945f,  0.030841381835986965f,
    -0.18703481171888114f,  -0.02798376941698385f,   0.6308807679295904f,
     0.7148465705525415f,    0.23037781330885523f};
__constant__ float c_HI[8] = {
    -0.23037781330885523f,   0.7148465705525415f,   -0.6308807679295904f,
    -0.02798376941698385f,   0.18703481171888114f,   0.030841381835986965f,
    -0.032883011666982945f, -0.010597401784997278f};

__device__ __forceinline__ float softt(float v, float t) {
    float av = fabsf(v);
    return (av > t) ? copysignf(av - t, v) : 0.0f;
}

// ---------------------------------------------------------------------------
// Kernel 1: per-row 7-level DWT -> soft threshold -> IDWT.
// One 128-thread block per row; contiguous chunks + sliding register windows.
// Levels: 1116 -> 561 -> 284 -> 145 -> 76 -> 41 -> 24 -> 15
// Data at offset 8 in buffers; xp[i] == buf[2+i] (left pad zeros at [2..7]).
// ---------------------------------------------------------------------------
__global__ __launch_bounds__(128) void wavelet_kernel(
    const float* __restrict__ x,
    const float* __restrict__ thr,
    float* __restrict__ recon)
{
    __shared__ __align__(16) float bufA[1140];
    __shared__ __align__(16) float bufB[1140];
    __shared__ __align__(16) float dbuf[1152];

    const int tid = threadIdx.x;
    const int row = blockIdx.x;
    const float t = fmaxf(thr[0], 0.01f);

    const int ns[8]   = {1116, 561, 284, 145, 76, 41, 24, 15};
    const int doff[7] = {0, 561, 845, 990, 1066, 1107, 1131};

    // Load row (vectorized): 1116 = 279 float4
    {
        const float4* xr = (const float4*)(x + (size_t)row * NLEN);
        float4* dst = (float4*)(bufA + 8);
        for (int i = tid; i < 279; i += 128) dst[i] = xr[i];
        if (tid < 6) bufA[2 + tid] = 0.0f;
        if (tid < 8) bufA[8 + NLEN + tid] = 0.0f;
    }
    __syncthreads();

    // ----- Analysis -----
    float* cur = bufA;
    float* nxt = bufB;
#pragma unroll
    for (int l = 0; l < 7; ++l) {
        const int m = ns[l + 1];
        float* dd = dbuf + doff[l];
        const int chunk = (m + 127) >> 7;
        const int j0 = tid * chunk;
        const int je = (j0 + chunk < m) ? (j0 + chunk) : m;
        if (j0 < je) {
            const float* p = cur + 2 + 2 * j0;
            float w0 = p[0], w1 = p[1], w2 = p[2], w3 = p[3];
            float w4 = p[4], w5 = p[5], w6 = p[6], w7 = p[7];
            int idx = 8;
            for (int j = j0; j < je; ++j) {
                float lo = w0 * c_LO[7];
                lo = fmaf(w1, c_LO[6], lo); lo = fmaf(w2, c_LO[5], lo);
                lo = fmaf(w3, c_LO[4], lo); lo = fmaf(w4, c_LO[3], lo);
                lo = fmaf(w5, c_LO[2], lo); lo = fmaf(w6, c_LO[1], lo);
                lo = fmaf(w7, c_LO[0], lo);
                float hi = w0 * c_HI[7];
                hi = fmaf(w1, c_HI[6], hi); hi = fmaf(w2, c_HI[5], hi);
                hi = fmaf(w3, c_HI[4], hi); hi = fmaf(w4, c_HI[3], hi);
                hi = fmaf(w5, c_HI[2], hi); hi = fmaf(w6, c_HI[1], hi);
                hi = fmaf(w7, c_HI[0], hi);
                nxt[8 + j] = lo;
                dd[j] = softt(hi, t);
                w0 = w2; w1 = w3; w2 = w4; w3 = w5; w4 = w6; w5 = w7;
                w6 = p[idx]; w7 = p[idx + 1]; idx += 2;   // lookahead (array slack)
            }
        }
        if (tid < 6) nxt[2 + tid] = 0.0f;
        if (tid < 8) nxt[8 + m + tid] = 0.0f;
        __syncthreads();
        float* tmp = cur; cur = nxt; nxt = tmp;
    }

    // soft-threshold final approx (len 15)
    if (tid < 15) cur[8 + tid] = softt(cur[8 + tid], t);
    __syncthreads();

    // ----- Synthesis -----
    // pair p: y[2p]   = sum a[p+q]*LO[2q+1] + d[p+q]*HI[2q+1]
    //         y[2p+1] = sum a[p+q]*LO[2q]   + d[p+q]*HI[2q]
    const float* abase = cur + 8;    // a7 at offset 8 of `cur`
    float* obase = nxt;              // other buffer, output at offset 0
#pragma unroll
    for (int l = 6; l >= 0; --l) {
        const int m = ns[l + 1];
        const int pairs = m - 3;     // olen = 2m-6
        const float* dd = dbuf + doff[l];
        const int chunk = (pairs + 127) >> 7;
        const int p0 = tid * chunk;
        const int pe = (p0 + chunk < pairs) ? (p0 + chunk) : pairs;
        if (p0 < pe) {
            float a0 = abase[p0], a1 = abase[p0 + 1], a2 = abase[p0 + 2], a3 = abase[p0 + 3];
            float d0 = dd[p0],    d1 = dd[p0 + 1],    d2 = dd[p0 + 2],    d3 = dd[p0 + 3];
            for (int p = p0; p < pe; ++p) {
                float ye = a0 * c_LO[1];
                ye = fmaf(a1, c_LO[3], ye); ye = fmaf(a2, c_LO[5], ye); ye = fmaf(a3, c_LO[7], ye);
                ye = fmaf(d0, c_HI[1], ye); ye = fmaf(d1, c_HI[3], ye);
                ye = fmaf(d2, c_HI[5], ye); ye = fmaf(d3, c_HI[7], ye);
                float yo = a0 * c_LO[0];
                yo = fmaf(a1, c_LO[2], yo); yo = fmaf(a2, c_LO[4], yo); yo = fmaf(a3, c_LO[6], yo);
                yo = fmaf(d0, c_HI[0], yo); yo = fmaf(d1, c_HI[2], yo);
                yo = fmaf(d2, c_HI[4], yo); yo = fmaf(d3, c_HI[6], yo);
                ((float2*)obase)[p] = make_float2(ye, yo);
                a0 = a1; a1 = a2; a2 = a3; a3 = abase[p + 4];   // lookahead ok
                d0 = d1; d1 = d2; d2 = d3; d3 = dd[p + 4];
            }
        }
        __syncthreads();
        const float* na = obase;
        abase = na;
        obase = (na == bufA) ? bufB : bufA;
    }

    // recon row = abase[0..1115]
    {
        float4* out = (float4*)(recon + (size_t)row * NLEN);
        const float4* a4 = (const float4*)abase;
        for (int i = tid; i < 279; i += 128) out[i] = a4[i];
    }
}

// ---------------------------------------------------------------------------
// W1 split precompute: hi/lo bf16 panels [70][128][16] (n padded to 128,
// k padded to 1120), k-panel-major so GEMM copies are contiguous.
// ---------------------------------------------------------------------------
#define KPANELS 70
#define BN 128
__device__ __nv_bfloat16 g_Bhi[KPANELS * BN * 16];
__device__ __nv_bfloat16 g_Blo[KPANELS * BN * 16];

__global__ __launch_bounds__(256) void w1_split_kernel(const float* __restrict__ W1)
{
    int i = blockIdx.x * 256 + threadIdx.x;
    if (i >= KPANELS * BN * 16) return;
    int kk = i & 15;
    int n  = (i >> 4) & 127;
    int p  = i >> 11;
    int k  = p * 16 + kk;
    float v = (n < HDIM && k < NLEN) ? W1[(size_t)n * NLEN + k] : 0.0f;
    __nv_bfloat16 h = __float2bfloat16(v);
    g_Bhi[i] = h;
    g_Blo[i] = __float2bfloat16(v - __bfloat162float(h));
}

// ---------------------------------------------------------------------------
// Kernel 2: wmma bf16 GEMM (split precision) + fused sigmoid/W2 reduction.
// Block: 64 rows x 128 cols (100 used), 8 warps = 4 m-tiles x 2 n-halves.
// D = Ahi*Bhi + Ahi*Blo + Alo*Bhi  (fp32 accum; alo*blo term dropped)
// ---------------------------------------------------------------------------
#define GBM 64
#define ALD 24      // A smem ld (elements)
#define BLD 24      // B smem ld (elements, col-major stride between n columns)
#define ELD 132     // epilogue smem ld (floats)

__global__ __launch_bounds__(256, 2) void mlp_wmma_kernel(
    const float* __restrict__ recon,
    const float* __restrict__ b1,
    const float* __restrict__ W2,
    const float* __restrict__ b2,
    float* __restrict__ reg)
{
    // Union: k-panel tiles (18432 B) / epilogue matrix (64x132 f32 = 33792 B)
    __shared__ __align__(16) char smem[GBM * ELD * 4];
    __shared__ float b1s[HDIM];
    __shared__ float w2s[HDIM];

    __nv_bfloat16* Ahi = (__nv_bfloat16*)(smem);            // [64][24]  3072 B
    __nv_bfloat16* Alo = (__nv_bfloat16*)(smem + 3072);     // [64][24]  3072 B
    __nv_bfloat16* Bhi = (__nv_bfloat16*)(smem + 6144);     // [128][24] 6144 B
    __nv_bfloat16* Blo = (__nv_bfloat16*)(smem + 12288);    // [128][24] 6144 B
    float* eps = (float*)smem;                               // [64][132]

    const int tid = threadIdx.x;
    const int wid = tid >> 5;
    const int wm = wid >> 1;      // m-tile 0..3
    const int wn = wid & 1;       // n-half 0..1
    const int row0 = blockIdx.x * GBM;

    if (tid < HDIM) { b1s[tid] = b1[tid]; w2s[tid] = W2[tid]; }

    wmma::fragment<wmma::accumulator, 16, 16, 16, float> acc[4];
#pragma unroll
    for (int nt = 0; nt < 4; ++nt) wmma::fill_fragment(acc[nt], 0.0f);

    const int r = tid >> 2;       // 0..63 : A row this thread loads
    const int q = tid & 3;        // 0..3  : 4-float chunk of the 16-k panel

    for (int p = 0; p < KPANELS; ++p) {
        __syncthreads();   // previous iteration's frag loads done

        // ---- A panel: 64 rows x 16 k fp32 -> bf16 hi/lo
        {
            const float* src = recon + (size_t)(row0 + r) * NLEN + p * 16 + q * 4;
            float4 v;
            if (p < KPANELS - 1 || q < 3) v = *(const float4*)src;   // last panel: k=1116..1119 zero
            else v = make_float4(0.f, 0.f, 0.f, 0.f);
            __nv_bfloat16 h0 = __float2bfloat16(v.x), h1 = __float2bfloat16(v.y);
            __nv_bfloat16 h2 = __float2bfloat16(v.z), h3 = __float2bfloat16(v.w);
            __nv_bfloat162 hp0 = __nv_bfloat162(h0, h1);
            __nv_bfloat162 hp1 = __nv_bfloat162(h2, h3);
            __nv_bfloat162 lp0 = __nv_bfloat162(
                __float2bfloat16(v.x - __bfloat162float(h0)),
                __float2bfloat16(v.y - __bfloat162float(h1)));
            __nv_bfloat162 lp1 = __nv_bfloat162(
                __float2bfloat16(v.z - __bfloat162float(h2)),
                __float2bfloat16(v.w - __bfloat162float(h3)));
            const int o = r * ALD + q * 4;       // element offset, 8B aligned
            *(__nv_bfloat162*)(Ahi + o)     = hp0;
            *(__nv_bfloat162*)(Ahi + o + 2) = hp1;
            *(__nv_bfloat162*)(Alo + o)     = lp0;
            *(__nv_bfloat162*)(Alo + o + 2) = lp1;
        }
        // ---- B panel: copy precomputed 128n x 16k (contiguous 4KB each)
        {
            const uint4 vh = ((const uint4*)g_Bhi)[p * 256 + tid];  // 8 bf16
            const uint4 vl = ((const uint4*)g_Blo)[p * 256 + tid];
            const int n = tid >> 1;
            const int ko = (tid & 1) * 8;
            *(uint4*)((char*)Bhi + (n * BLD + ko) * 2) = vh;   // 16B aligned
            *(uint4*)((char*)Blo + (n * BLD + ko) * 2) = vl;
        }
        __syncthreads();

        wmma::fragment<wmma::matrix_a, 16, 16, 16, __nv_bfloat16, wmma::row_major> fa_hi, fa_lo;
        wmma::load_matrix_sync(fa_hi, Ahi + wm * 16 * ALD, ALD);
        wmma::load_matrix_sync(fa_lo, Alo + wm * 16 * ALD, ALD);
#pragma unroll
        for (int nt = 0; nt < 4; ++nt) {
            const int n0 = (wn * 4 + nt) * 16;
            wmma::fragment<wmma::matrix_b, 16, 16, 16, __nv_bfloat16, wmma::col_major> fb_hi, fb_lo;
            wmma::load_matrix_sync(fb_hi, Bhi + n0 * BLD, BLD);
            wmma::load_matrix_sync(fb_lo, Blo + n0 * BLD, BLD);
            wmma::mma_sync(acc[nt], fa_hi, fb_hi, acc[nt]);
            wmma::mma_sync(acc[nt], fa_hi, fb_lo, acc[nt]);
            wmma::mma_sync(acc[nt], fa_lo, fb_hi, acc[nt]);
        }
    }

    __syncthreads();   // done with tile buffers; reuse as epilogue matrix
#pragma unroll
    for (int nt = 0; nt < 4; ++nt) {
        wmma::store_matrix_sync(eps + wm * 16 * ELD + (wn * 4 + nt) * 16,
                                acc[nt], ELD, wmma::mem_row_major);
    }
    __syncthreads();

    // Epilogue: 4 threads per row, 25 cols each, shfl reduce.
    {
        const float* er = eps + r * ELD;
        float s = 0.0f;
        const int c0 = q * 25;
#pragma unroll
        for (int c = 0; c < 25; ++c) {
            float pre = er[c0 + c] + b1s[c0 + c];
            float h = 1.0f / (1.0f + __expf(-pre));
            s = fmaf(h, w2s[c0 + c], s);
        }
        s += __shfl_xor_sync(0xFFFFFFFFu, s, 1);
        s += __shfl_xor_sync(0xFFFFFFFFu, s, 2);
        if (q == 0) reg[row0 + r] = s + b2[0];
    }
}

// ---------------------------------------------------------------------------
extern "C" void kernel_launch(void* const* d_in, const int* in_sizes, int n_in,
                              void* d_out, int out_size)
{
    const float* x   = (const float*)d_in[0];
    const float* thr = (const float*)d_in[1];
    const float* W1  = (const float*)d_in[2];
    const float* b1  = (const float*)d_in[3];
    const float* W2  = (const float*)d_in[4];
    const float* b2  = (const float*)d_in[5];

    float* recon = (float*)d_out;
    float* reg   = (float*)d_out + (size_t)BATCH * NLEN;

    w1_split_kernel<<<(KPANELS * BN * 16 + 255) / 256, 256>>>(W1);
    wavelet_kernel<<<BATCH, 128>>>(x, thr, recon);
    mlp_wmma_kernel<<<BATCH / GBM, 256>>>(recon, b1, W2, b2, reg);
}